// round 1
// baseline (speedup 1.0000x reference)
#include <cuda_runtime.h>
#include <cuda_bf16.h>
#include <cstdint>
#include <cstddef>

// ---------------------------------------------------------------------------
// Problem constants
//   hidden: [4, 2048, 1024]  context: [4, 77, 768]
//   HEADS=16, D_HEAD=64, INNER=1024, FF_INNER=4096
// ---------------------------------------------------------------------------
#define BROWS   8192      // B*S = 4*2048
#define CROWS   308       // B*T = 4*77
#define DIM     1024
#define CTXD    768
#define FFI     4096
#define SEQ     2048
#define TCTX    77
#define NHEADS  16
#define DHEAD   64
#define ATTN_SCALE 0.125f // 64^-0.5

// ---------------------------------------------------------------------------
// Scratch (device globals — no runtime allocation allowed)
// ---------------------------------------------------------------------------
__device__ float g_xn  [(size_t)BROWS * DIM];          // normalized activations
__device__ float g_q   [(size_t)BROWS * DIM];
__device__ float g_k   [(size_t)BROWS * DIM];
__device__ float g_v   [(size_t)BROWS * DIM];
__device__ float g_attn[(size_t)BROWS * DIM];          // attention out (pre-proj)
__device__ float g_h   [(size_t)BROWS * DIM];          // running hidden
__device__ float g_ff  [(size_t)BROWS * 2 * FFI];      // FF1 output (8192 wide)
__device__ float g_gg  [(size_t)BROWS * FFI];          // GEGLU output

// ---------------------------------------------------------------------------
// LayerNorm: one block per row, 256 threads, dim = 1024 (4 floats/thread)
// ---------------------------------------------------------------------------
__global__ __launch_bounds__(256) void ln_kernel(
    const float* __restrict__ x, float* __restrict__ y,
    const float* __restrict__ gam, const float* __restrict__ bet)
{
    __shared__ float red[16];
    const int row = blockIdx.x;
    const int t = threadIdx.x;
    const float4 xv = reinterpret_cast<const float4*>(x + (size_t)row * DIM)[t];

    float s  = xv.x + xv.y + xv.z + xv.w;
    float sq = xv.x*xv.x + xv.y*xv.y + xv.z*xv.z + xv.w*xv.w;
    #pragma unroll
    for (int w = 16; w > 0; w >>= 1) {
        s  += __shfl_xor_sync(0xffffffffu, s,  w);
        sq += __shfl_xor_sync(0xffffffffu, sq, w);
    }
    const int wid = t >> 5, lid = t & 31;
    if (lid == 0) { red[wid] = s; red[8 + wid] = sq; }
    __syncthreads();
    if (t < 32) {
        float a  = (lid < 8) ? red[lid]     : 0.f;
        float aq = (lid < 8) ? red[8 + lid] : 0.f;
        #pragma unroll
        for (int w = 4; w > 0; w >>= 1) {
            a  += __shfl_xor_sync(0xffffffffu, a,  w);
            aq += __shfl_xor_sync(0xffffffffu, aq, w);
        }
        if (lid == 0) { red[0] = a; red[8] = aq; }
    }
    __syncthreads();
    const float mean = red[0] * (1.f / DIM);
    const float var  = red[8] * (1.f / DIM) - mean * mean;
    const float inv  = rsqrtf(var + 1e-5f);

    const float4 gv = reinterpret_cast<const float4*>(gam)[t];
    const float4 bv = reinterpret_cast<const float4*>(bet)[t];
    float4 o;
    o.x = (xv.x - mean) * inv * gv.x + bv.x;
    o.y = (xv.y - mean) * inv * gv.y + bv.y;
    o.z = (xv.z - mean) * inv * gv.z + bv.z;
    o.w = (xv.w - mean) * inv * gv.w + bv.w;
    reinterpret_cast<float4*>(y + (size_t)row * DIM)[t] = o;
}

// ---------------------------------------------------------------------------
// Tiled fp32 GEMM:  C[M,N] = A[M,K] @ W[K,N] (+bias) (+residual)
// 128x128 tile, BK=16, 256 threads, each computes 8x8 as 4+4 split rows/cols.
// K must be multiple of 16, N multiple of 128. M guarded.
// ---------------------------------------------------------------------------
__global__ __launch_bounds__(256) void gemm_kernel(
    const float* __restrict__ A, const float* __restrict__ W,
    const float* __restrict__ bias, const float* __restrict__ res,
    float* __restrict__ C, int M, int N, int K)
{
    __shared__ float As[16][132];   // transposed A tile, padded (4 -> 2-way STS)
    __shared__ float Bs[16][128];

    const int tid = threadIdx.x;
    const int ty = tid >> 4, tx = tid & 15;
    const int m0 = blockIdx.y << 7, n0 = blockIdx.x << 7;

    float acc[8][8];
    #pragma unroll
    for (int i = 0; i < 8; i++)
        #pragma unroll
        for (int j = 0; j < 8; j++) acc[i][j] = 0.f;

    const int ar = tid >> 2;          // 0..63
    const int ac = (tid & 3) << 2;    // 0,4,8,12
    const int br = tid >> 5;          // 0..7
    const int bc = (tid & 31) << 2;   // 0..124

    for (int k0 = 0; k0 < K; k0 += 16) {
        #pragma unroll
        for (int i = 0; i < 2; i++) {
            const int r = ar + i * 64;
            float4 va = make_float4(0.f, 0.f, 0.f, 0.f);
            if (m0 + r < M)
                va = *reinterpret_cast<const float4*>(A + (size_t)(m0 + r) * K + k0 + ac);
            As[ac + 0][r] = va.x; As[ac + 1][r] = va.y;
            As[ac + 2][r] = va.z; As[ac + 3][r] = va.w;
        }
        #pragma unroll
        for (int i = 0; i < 2; i++) {
            const int r = br + i * 8;
            *reinterpret_cast<float4*>(&Bs[r][bc]) =
                *reinterpret_cast<const float4*>(W + (size_t)(k0 + r) * N + n0 + bc);
        }
        __syncthreads();
        #pragma unroll
        for (int kk = 0; kk < 16; kk++) {
            float a[8], b[8];
            *reinterpret_cast<float4*>(a)     = *reinterpret_cast<const float4*>(&As[kk][ty * 4]);
            *reinterpret_cast<float4*>(a + 4) = *reinterpret_cast<const float4*>(&As[kk][64 + ty * 4]);
            *reinterpret_cast<float4*>(b)     = *reinterpret_cast<const float4*>(&Bs[kk][tx * 4]);
            *reinterpret_cast<float4*>(b + 4) = *reinterpret_cast<const float4*>(&Bs[kk][64 + tx * 4]);
            #pragma unroll
            for (int i = 0; i < 8; i++)
                #pragma unroll
                for (int j = 0; j < 8; j++)
                    acc[i][j] += a[i] * b[j];
        }
        __syncthreads();
    }

    #pragma unroll
    for (int i = 0; i < 8; i++) {
        const int r = m0 + ((i < 4) ? (ty * 4 + i) : (64 + ty * 4 + i - 4));
        if (r >= M) continue;
        #pragma unroll
        for (int jh = 0; jh < 2; jh++) {
            const int c = n0 + jh * 64 + tx * 4;
            float4 vv;
            vv.x = acc[i][jh * 4 + 0]; vv.y = acc[i][jh * 4 + 1];
            vv.z = acc[i][jh * 4 + 2]; vv.w = acc[i][jh * 4 + 3];
            if (bias) {
                vv.x += bias[c]; vv.y += bias[c + 1];
                vv.z += bias[c + 2]; vv.w += bias[c + 3];
            }
            if (res) {
                const float4 rv = *reinterpret_cast<const float4*>(res + (size_t)r * N + c);
                vv.x += rv.x; vv.y += rv.y; vv.z += rv.z; vv.w += rv.w;
            }
            *reinterpret_cast<float4*>(C + (size_t)r * N + c) = vv;
        }
    }
}

// ---------------------------------------------------------------------------
// Flash attention (fp32). Layout: Q/K/V/O are [B*Seq, HEADS*DHEAD] row-major.
// Grid: (Sq/64, HEADS, B). Block: 256 threads.
// Thread (tq=tid/16, tk=tid%16) owns 4x4 of the 64x64 score tile and
// 4 q-rows x 4 head-dims of the output.
// Dynamic smem: QsT[64][68] KsT[64][68] PsT[64][68] Vs[64][64]
// ---------------------------------------------------------------------------
#define ATTN_SMEM_BYTES ((3 * 64 * 68 + 64 * 64) * 4)

__global__ __launch_bounds__(256) void attn_kernel(
    const float* __restrict__ Q, const float* __restrict__ K,
    const float* __restrict__ V, float* __restrict__ O,
    int Sq, int Sk)
{
    extern __shared__ float smem[];
    float (*QsT)[68] = reinterpret_cast<float (*)[68]>(smem);
    float (*KsT)[68] = reinterpret_cast<float (*)[68]>(smem + 64 * 68);
    float (*PsT)[68] = reinterpret_cast<float (*)[68]>(smem + 2 * 64 * 68);
    float (*Vs)[64]  = reinterpret_cast<float (*)[64]>(smem + 3 * 64 * 68);

    const int tid = threadIdx.x;
    const int tq = tid >> 4;      // 0..15 : q rows tq*4..tq*4+3
    const int tk = tid & 15;      // 0..15 : k cols / dims tk*4..tk*4+3
    const int h = blockIdx.y, b = blockIdx.z;
    const int q0 = blockIdx.x * 64;
    const size_t qoff = (size_t)b * Sq * DIM + (size_t)h * DHEAD;
    const size_t koff = (size_t)b * Sk * DIM + (size_t)h * DHEAD;

    // Load Q tile transposed: QsT[d][q]
    for (int i = tid; i < 64 * 16; i += 256) {
        const int r = i >> 4, c4 = (i & 15) << 2;
        const float4 v = *reinterpret_cast<const float4*>(
            Q + qoff + (size_t)(q0 + r) * DIM + c4);
        QsT[c4 + 0][r] = v.x; QsT[c4 + 1][r] = v.y;
        QsT[c4 + 2][r] = v.z; QsT[c4 + 3][r] = v.w;
    }

    float o[4][4];
    float m[4], l[4];
    #pragma unroll
    for (int i = 0; i < 4; i++) {
        m[i] = -1e30f; l[i] = 0.f;
        #pragma unroll
        for (int j = 0; j < 4; j++) o[i][j] = 0.f;
    }

    const int nkt = (Sk + 63) >> 6;
    for (int kt = 0; kt < nkt; kt++) {
        __syncthreads();
        // Load K (transposed) + V (row-major); zero-pad rows >= Sk
        for (int i = tid; i < 64 * 16; i += 256) {
            const int r = i >> 4, c4 = (i & 15) << 2;
            const int gr = kt * 64 + r;
            float4 kv = make_float4(0.f, 0.f, 0.f, 0.f);
            float4 vv = make_float4(0.f, 0.f, 0.f, 0.f);
            if (gr < Sk) {
                kv = *reinterpret_cast<const float4*>(K + koff + (size_t)gr * DIM + c4);
                vv = *reinterpret_cast<const float4*>(V + koff + (size_t)gr * DIM + c4);
            }
            KsT[c4 + 0][r] = kv.x; KsT[c4 + 1][r] = kv.y;
            KsT[c4 + 2][r] = kv.z; KsT[c4 + 3][r] = kv.w;
            *reinterpret_cast<float4*>(&Vs[r][c4]) = vv;
        }
        __syncthreads();

        // Scores: s[qq][kk] = Q[tq*4+qq] . K[tk*4+kk]
        float s[4][4];
        #pragma unroll
        for (int i = 0; i < 4; i++)
            #pragma unroll
            for (int j = 0; j < 4; j++) s[i][j] = 0.f;
        #pragma unroll 8
        for (int d = 0; d < 64; d++) {
            float qa[4], kb[4];
            *reinterpret_cast<float4*>(qa) = *reinterpret_cast<const float4*>(&QsT[d][tq * 4]);
            *reinterpret_cast<float4*>(kb) = *reinterpret_cast<const float4*>(&KsT[d][tk * 4]);
            #pragma unroll
            for (int i = 0; i < 4; i++)
                #pragma unroll
                for (int j = 0; j < 4; j++)
                    s[i][j] += qa[i] * kb[j];
        }
        // scale + mask invalid keys
        #pragma unroll
        for (int qq = 0; qq < 4; qq++)
            #pragma unroll
            for (int kk = 0; kk < 4; kk++) {
                float sv = s[qq][kk] * ATTN_SCALE;
                if (kt * 64 + tk * 4 + kk >= Sk) sv = -1e30f;
                s[qq][kk] = sv;
            }

        // Online softmax per q-row (reduce over 16 tk lanes, same warp half)
        float corr[4];
        #pragma unroll
        for (int qq = 0; qq < 4; qq++) {
            float rmax = fmaxf(fmaxf(s[qq][0], s[qq][1]), fmaxf(s[qq][2], s[qq][3]));
            #pragma unroll
            for (int w = 1; w < 16; w <<= 1)
                rmax = fmaxf(rmax, __shfl_xor_sync(0xffffffffu, rmax, w));
            const float mn = fmaxf(m[qq], rmax);
            const float c = __expf(m[qq] - mn);
            float rs = 0.f;
            #pragma unroll
            for (int kk = 0; kk < 4; kk++) {
                const float p = __expf(s[qq][kk] - mn);
                s[qq][kk] = p; rs += p;
            }
            #pragma unroll
            for (int w = 1; w < 16; w <<= 1)
                rs += __shfl_xor_sync(0xffffffffu, rs, w);
            l[qq] = l[qq] * c + rs;
            m[qq] = mn;
            corr[qq] = c;
        }
        // Publish probabilities transposed: PsT[k][q]
        #pragma unroll
        for (int kk = 0; kk < 4; kk++)
            #pragma unroll
            for (int qq = 0; qq < 4; qq++)
                PsT[tk * 4 + kk][tq * 4 + qq] = s[qq][kk];
        // Rescale accumulator
        #pragma unroll
        for (int qq = 0; qq < 4; qq++)
            #pragma unroll
            for (int dd = 0; dd < 4; dd++)
                o[qq][dd] *= corr[qq];
        __syncthreads();

        // O accumulate: o[qq][dd] += sum_j P[q][j] * V[j][tk*4+dd]
        #pragma unroll 8
        for (int j = 0; j < 64; j++) {
            float pa[4], vb[4];
            *reinterpret_cast<float4*>(pa) = *reinterpret_cast<const float4*>(&PsT[j][tq * 4]);
            *reinterpret_cast<float4*>(vb) = *reinterpret_cast<const float4*>(&Vs[j][tk * 4]);
            #pragma unroll
            for (int qq = 0; qq < 4; qq++)
                #pragma unroll
                for (int dd = 0; dd < 4; dd++)
                    o[qq][dd] += pa[qq] * vb[dd];
        }
    }

    // Epilogue
    #pragma unroll
    for (int qq = 0; qq < 4; qq++) {
        const float inv = 1.f / l[qq];
        float4 v;
        v.x = o[qq][0] * inv; v.y = o[qq][1] * inv;
        v.z = o[qq][2] * inv; v.w = o[qq][3] * inv;
        *reinterpret_cast<float4*>(
            O + qoff + (size_t)(q0 + tq * 4 + qq) * DIM + tk * 4) = v;
    }
}

// ---------------------------------------------------------------------------
// GEGLU: out[r][c] = lin * gelu_tanh(gate), lin = ff[r][c], gate = ff[r][c+FFI]
// JAX default gelu is the tanh approximation.
// ---------------------------------------------------------------------------
__device__ __forceinline__ float gelu_tanh(float x) {
    const float x3 = x * x * x;
    return 0.5f * x * (1.f + tanhf(0.7978845608028654f * (x + 0.044715f * x3)));
}

__global__ __launch_bounds__(256) void geglu_kernel(
    const float* __restrict__ ff, float* __restrict__ out)
{
    const int r = blockIdx.y;
    const int c = (blockIdx.x * 256 + threadIdx.x) << 2;
    const float4 lin = *reinterpret_cast<const float4*>(ff + (size_t)r * (2 * FFI) + c);
    const float4 gt  = *reinterpret_cast<const float4*>(ff + (size_t)r * (2 * FFI) + FFI + c);
    float4 o;
    o.x = lin.x * gelu_tanh(gt.x);
    o.y = lin.y * gelu_tanh(gt.y);
    o.z = lin.z * gelu_tanh(gt.z);
    o.w = lin.w * gelu_tanh(gt.w);
    *reinterpret_cast<float4*>(out + (size_t)r * FFI + c) = o;
}

// ---------------------------------------------------------------------------
// Launch sequence
// ---------------------------------------------------------------------------
extern "C" void kernel_launch(void* const* d_in, const int* in_sizes, int n_in,
                              void* d_out, int out_size)
{
    const float* hs   = (const float*)d_in[0];
    const float* ctx  = (const float*)d_in[1];
    const float* wq1  = (const float*)d_in[2];
    const float* wk1  = (const float*)d_in[3];
    const float* wv1  = (const float*)d_in[4];
    const float* wo1  = (const float*)d_in[5];
    const float* bo1  = (const float*)d_in[6];
    const float* wq2  = (const float*)d_in[7];
    const float* wk2  = (const float*)d_in[8];
    const float* wv2  = (const float*)d_in[9];
    const float* wo2  = (const float*)d_in[10];
    const float* bo2  = (const float*)d_in[11];
    const float* wff1 = (const float*)d_in[12];
    const float* bff1 = (const float*)d_in[13];
    const float* wff2 = (const float*)d_in[14];
    const float* bff2 = (const float*)d_in[15];
    const float* ln1g = (const float*)d_in[16];
    const float* ln1b = (const float*)d_in[17];
    const float* ln2g = (const float*)d_in[18];
    const float* ln2b = (const float*)d_in[19];
    const float* ln3g = (const float*)d_in[20];
    const float* ln3b = (const float*)d_in[21];
    float* out = (float*)d_out;

    float *xn, *q, *k, *v, *attnb, *h, *ff, *gg;
    cudaGetSymbolAddress((void**)&xn,    g_xn);
    cudaGetSymbolAddress((void**)&q,     g_q);
    cudaGetSymbolAddress((void**)&k,     g_k);
    cudaGetSymbolAddress((void**)&v,     g_v);
    cudaGetSymbolAddress((void**)&attnb, g_attn);
    cudaGetSymbolAddress((void**)&h,     g_h);
    cudaGetSymbolAddress((void**)&ff,    g_ff);
    cudaGetSymbolAddress((void**)&gg,    g_gg);

    static bool attr_set = false;
    if (!attr_set) {
        cudaFuncSetAttribute(attn_kernel,
                             cudaFuncAttributeMaxDynamicSharedMemorySize,
                             ATTN_SMEM_BYTES);
        attr_set = true;
    }

    const dim3 blk(256);
    const dim3 g_1024(DIM / 128, BROWS / 128);     // (8, 64)
    const dim3 g_ctx (DIM / 128, (CROWS + 127) / 128); // (8, 3)
    const dim3 g_ff1 ((2 * FFI) / 128, BROWS / 128);   // (64, 64)
    const dim3 g_attng(SEQ / 64, NHEADS, 4);       // (32, 16, 4)

    // ---- self-attention block ----
    ln_kernel<<<BROWS, blk>>>(hs, xn, ln1g, ln1b);
    gemm_kernel<<<g_1024, blk>>>(xn, wq1, nullptr, nullptr, q, BROWS, DIM, DIM);
    gemm_kernel<<<g_1024, blk>>>(xn, wk1, nullptr, nullptr, k, BROWS, DIM, DIM);
    gemm_kernel<<<g_1024, blk>>>(xn, wv1, nullptr, nullptr, v, BROWS, DIM, DIM);
    attn_kernel<<<g_attng, blk, ATTN_SMEM_BYTES>>>(q, k, v, attnb, SEQ, SEQ);
    gemm_kernel<<<g_1024, blk>>>(attnb, wo1, bo1, hs, h, BROWS, DIM, DIM);

    // ---- cross-attention block ----
    ln_kernel<<<BROWS, blk>>>(h, xn, ln2g, ln2b);
    gemm_kernel<<<g_1024, blk>>>(xn, wq2, nullptr, nullptr, q, BROWS, DIM, DIM);
    gemm_kernel<<<g_ctx,  blk>>>(ctx, wk2, nullptr, nullptr, k, CROWS, DIM, CTXD);
    gemm_kernel<<<g_ctx,  blk>>>(ctx, wv2, nullptr, nullptr, v, CROWS, DIM, CTXD);
    attn_kernel<<<g_attng, blk, ATTN_SMEM_BYTES>>>(q, k, v, attnb, SEQ, TCTX);
    gemm_kernel<<<g_1024, blk>>>(attnb, wo2, bo2, h, h, BROWS, DIM, DIM);

    // ---- GEGLU feed-forward ----
    ln_kernel<<<BROWS, blk>>>(h, xn, ln3g, ln3b);
    gemm_kernel<<<g_ff1, blk>>>(xn, wff1, bff1, nullptr, ff, BROWS, 2 * FFI, DIM);
    geglu_kernel<<<dim3(FFI / 1024, BROWS), blk>>>(ff, gg);
    gemm_kernel<<<g_1024, blk>>>(gg, wff2, bff2, h, out, BROWS, DIM, FFI);
}

// round 2
// speedup vs baseline: 1.6952x; 1.6952x over previous
#include <cuda_runtime.h>
#include <cuda_bf16.h>
#include <cstdint>
#include <cstddef>

// ---------------------------------------------------------------------------
// Problem constants
// ---------------------------------------------------------------------------
#define BROWS   8192      // B*S = 4*2048
#define CROWS   308       // B*T = 4*77
#define DIM     1024
#define CTXD    768
#define FFI     4096
#define SEQ     2048
#define TCTX    77
#define NHEADS  16
#define DHEAD   64
#define ATTN_SCALE 0.125f

// ---------------------------------------------------------------------------
// Scratch (device globals)
// ---------------------------------------------------------------------------
__device__ float g_xn  [(size_t)BROWS * DIM];
__device__ float g_q   [(size_t)BROWS * DIM];
__device__ float g_k   [(size_t)BROWS * DIM];
__device__ float g_v   [(size_t)BROWS * DIM];
__device__ float g_attn[(size_t)BROWS * DIM];
__device__ float g_h   [(size_t)BROWS * DIM];
__device__ float g_ff  [(size_t)BROWS * 2 * FFI];
__device__ float g_gg  [(size_t)BROWS * FFI];

// ---------------------------------------------------------------------------
// LayerNorm (unchanged)
// ---------------------------------------------------------------------------
__global__ __launch_bounds__(256) void ln_kernel(
    const float* __restrict__ x, float* __restrict__ y,
    const float* __restrict__ gam, const float* __restrict__ bet)
{
    __shared__ float red[16];
    const int row = blockIdx.x;
    const int t = threadIdx.x;
    const float4 xv = reinterpret_cast<const float4*>(x + (size_t)row * DIM)[t];

    float s  = xv.x + xv.y + xv.z + xv.w;
    float sq = xv.x*xv.x + xv.y*xv.y + xv.z*xv.z + xv.w*xv.w;
    #pragma unroll
    for (int w = 16; w > 0; w >>= 1) {
        s  += __shfl_xor_sync(0xffffffffu, s,  w);
        sq += __shfl_xor_sync(0xffffffffu, sq, w);
    }
    const int wid = t >> 5, lid = t & 31;
    if (lid == 0) { red[wid] = s; red[8 + wid] = sq; }
    __syncthreads();
    if (t < 32) {
        float a  = (lid < 8) ? red[lid]     : 0.f;
        float aq = (lid < 8) ? red[8 + lid] : 0.f;
        #pragma unroll
        for (int w = 4; w > 0; w >>= 1) {
            a  += __shfl_xor_sync(0xffffffffu, a,  w);
            aq += __shfl_xor_sync(0xffffffffu, aq, w);
        }
        if (lid == 0) { red[0] = a; red[8] = aq; }
    }
    __syncthreads();
    const float mean = red[0] * (1.f / DIM);
    const float var  = red[8] * (1.f / DIM) - mean * mean;
    const float inv  = rsqrtf(var + 1e-5f);

    const float4 gv = reinterpret_cast<const float4*>(gam)[t];
    const float4 bv = reinterpret_cast<const float4*>(bet)[t];
    float4 o;
    o.x = (xv.x - mean) * inv * gv.x + bv.x;
    o.y = (xv.y - mean) * inv * gv.y + bv.y;
    o.z = (xv.z - mean) * inv * gv.z + bv.z;
    o.w = (xv.w - mean) * inv * gv.w + bv.w;
    reinterpret_cast<float4*>(y + (size_t)row * DIM)[t] = o;
}

// ---------------------------------------------------------------------------
// tf32 tensor-core GEMM: C[M,N] = A[M,K] @ W[K,N] (+bias) (+residual)
// 128x128x16 CTA tile, 8 warps (2x4), warp tile 64x32 via m16n8k8 tf32 mma.
// fp32 -> tf32 (round-to-nearest) at smem store. Double-buffered smem.
// K % 16 == 0, N % 128 == 0, M guarded.
// ---------------------------------------------------------------------------
#define BM 128
#define BN 128
#define BKT 16
#define BKP 20     // A smem row pitch (conflict-free for a-frag pattern)
#define BNP 136    // B smem row pitch (136 mod 32 banks = 8 -> conflict-free)

__device__ __forceinline__ unsigned f2tf32(float f) {
    unsigned u;
    asm("cvt.rna.tf32.f32 %0, %1;" : "=r"(u) : "f"(f));
    return u;
}

__device__ __forceinline__ void mma_tf32(float c[4], const unsigned a[4], const unsigned b[2]) {
    asm volatile(
        "mma.sync.aligned.m16n8k8.row.col.f32.tf32.tf32.f32 "
        "{%0,%1,%2,%3}, {%4,%5,%6,%7}, {%8,%9}, {%0,%1,%2,%3};\n"
        : "+f"(c[0]), "+f"(c[1]), "+f"(c[2]), "+f"(c[3])
        : "r"(a[0]), "r"(a[1]), "r"(a[2]), "r"(a[3]),
          "r"(b[0]), "r"(b[1]));
}

__global__ __launch_bounds__(256, 2) void gemm_tf32(
    const float* __restrict__ A, const float* __restrict__ W,
    const float* __restrict__ bias, const float* __restrict__ res,
    float* __restrict__ C, int M, int N, int K)
{
    __shared__ __align__(16) unsigned As[2][BM * BKP];
    __shared__ __align__(16) unsigned Bs[2][BKT * BNP];

    const int tid  = threadIdx.x;
    const int warp = tid >> 5, lane = tid & 31;
    const int wm = (warp & 1) * 64;       // warp M offset (2 warps along M)
    const int wn = (warp >> 1) * 32;      // warp N offset (4 warps along N)
    const int grp = lane >> 2, tig = lane & 3;
    const int m0 = blockIdx.y << 7, n0 = blockIdx.x << 7;

    // gmem staging mapping
    const int arow = tid >> 1;            // 0..127
    const int ac4  = (tid & 1) * 2;       // float4 idx base {0,2}
    const int brow = tid >> 4;            // 0..15
    const int bc4  = (tid & 15) * 2;      // float4 idx base 0..30

    float acc[4][4][4];
    #pragma unroll
    for (int i = 0; i < 4; i++)
        #pragma unroll
        for (int j = 0; j < 4; j++)
            #pragma unroll
            for (int r = 0; r < 4; r++) acc[i][j][r] = 0.f;

    float4 ra[2], rb[2];
    const bool a_ok = (m0 + arow) < M;

    auto g_load = [&](int k0) {
        const float* pa = A + (size_t)(m0 + arow) * K + k0;
        ra[0] = a_ok ? reinterpret_cast<const float4*>(pa)[ac4]     : make_float4(0,0,0,0);
        ra[1] = a_ok ? reinterpret_cast<const float4*>(pa)[ac4 + 1] : make_float4(0,0,0,0);
        const float* pb = W + (size_t)(k0 + brow) * N + n0;
        rb[0] = reinterpret_cast<const float4*>(pb)[bc4];
        rb[1] = reinterpret_cast<const float4*>(pb)[bc4 + 1];
    };
    auto s_store = [&](int s) {
        #pragma unroll
        for (int i = 0; i < 2; i++) {
            const float4 v = ra[i];
            uint4 u = make_uint4(f2tf32(v.x), f2tf32(v.y), f2tf32(v.z), f2tf32(v.w));
            *reinterpret_cast<uint4*>(&As[s][arow * BKP + (ac4 + i) * 4]) = u;
        }
        #pragma unroll
        for (int i = 0; i < 2; i++) {
            const float4 v = rb[i];
            uint4 u = make_uint4(f2tf32(v.x), f2tf32(v.y), f2tf32(v.z), f2tf32(v.w));
            *reinterpret_cast<uint4*>(&Bs[s][brow * BNP + (bc4 + i) * 4]) = u;
        }
    };

    g_load(0);
    s_store(0);
    __syncthreads();

    const int niter = K / BKT;
    int stage = 0;
    for (int it = 0; it < niter; it++) {
        const bool has_next = (it + 1) < niter;
        if (has_next) g_load((it + 1) * BKT);

        #pragma unroll
        for (int ks = 0; ks < 16; ks += 8) {
            unsigned a[4][4], b[4][2];
            #pragma unroll
            for (int mi = 0; mi < 4; mi++) {
                const int r = wm + mi * 16 + grp;
                a[mi][0] = As[stage][r * BKP + ks + tig];
                a[mi][1] = As[stage][(r + 8) * BKP + ks + tig];
                a[mi][2] = As[stage][r * BKP + ks + tig + 4];
                a[mi][3] = As[stage][(r + 8) * BKP + ks + tig + 4];
            }
            #pragma unroll
            for (int nj = 0; nj < 4; nj++) {
                const int c = wn + nj * 8 + grp;
                b[nj][0] = Bs[stage][(ks + tig) * BNP + c];
                b[nj][1] = Bs[stage][(ks + tig + 4) * BNP + c];
            }
            #pragma unroll
            for (int mi = 0; mi < 4; mi++)
                #pragma unroll
                for (int nj = 0; nj < 4; nj++)
                    mma_tf32(acc[mi][nj], a[mi], b[nj]);
        }

        if (has_next) s_store(stage ^ 1);
        __syncthreads();
        stage ^= 1;
    }

    // Epilogue: each mma frag -> two float2 stores (rows grp, grp+8)
    #pragma unroll
    for (int mi = 0; mi < 4; mi++) {
        #pragma unroll
        for (int half = 0; half < 2; half++) {
            const int r = m0 + wm + mi * 16 + grp + half * 8;
            if (r >= M) continue;
            #pragma unroll
            for (int nj = 0; nj < 4; nj++) {
                const int c = n0 + wn + nj * 8 + tig * 2;
                float2 v;
                v.x = acc[mi][nj][half * 2 + 0];
                v.y = acc[mi][nj][half * 2 + 1];
                if (bias) { v.x += bias[c]; v.y += bias[c + 1]; }
                if (res) {
                    const float2 rv = *reinterpret_cast<const float2*>(res + (size_t)r * N + c);
                    v.x += rv.x; v.y += rv.y;
                }
                *reinterpret_cast<float2*>(C + (size_t)r * N + c) = v;
            }
        }
    }
}

// ---------------------------------------------------------------------------
// Flash attention (fp32 SIMT, unchanged from R1)
// ---------------------------------------------------------------------------
#define ATTN_SMEM_BYTES ((3 * 64 * 68 + 64 * 64) * 4)

__global__ __launch_bounds__(256) void attn_kernel(
    const float* __restrict__ Q, const float* __restrict__ K,
    const float* __restrict__ V, float* __restrict__ O,
    int Sq, int Sk)
{
    extern __shared__ float smem[];
    float (*QsT)[68] = reinterpret_cast<float (*)[68]>(smem);
    float (*KsT)[68] = reinterpret_cast<float (*)[68]>(smem + 64 * 68);
    float (*PsT)[68] = reinterpret_cast<float (*)[68]>(smem + 2 * 64 * 68);
    float (*Vs)[64]  = reinterpret_cast<float (*)[64]>(smem + 3 * 64 * 68);

    const int tid = threadIdx.x;
    const int tq = tid >> 4;
    const int tk = tid & 15;
    const int h = blockIdx.y, b = blockIdx.z;
    const int q0 = blockIdx.x * 64;
    const size_t qoff = (size_t)b * Sq * DIM + (size_t)h * DHEAD;
    const size_t koff = (size_t)b * Sk * DIM + (size_t)h * DHEAD;

    for (int i = tid; i < 64 * 16; i += 256) {
        const int r = i >> 4, c4 = (i & 15) << 2;
        const float4 v = *reinterpret_cast<const float4*>(
            Q + qoff + (size_t)(q0 + r) * DIM + c4);
        QsT[c4 + 0][r] = v.x; QsT[c4 + 1][r] = v.y;
        QsT[c4 + 2][r] = v.z; QsT[c4 + 3][r] = v.w;
    }

    float o[4][4];
    float m[4], l[4];
    #pragma unroll
    for (int i = 0; i < 4; i++) {
        m[i] = -1e30f; l[i] = 0.f;
        #pragma unroll
        for (int j = 0; j < 4; j++) o[i][j] = 0.f;
    }

    const int nkt = (Sk + 63) >> 6;
    for (int kt = 0; kt < nkt; kt++) {
        __syncthreads();
        for (int i = tid; i < 64 * 16; i += 256) {
            const int r = i >> 4, c4 = (i & 15) << 2;
            const int gr = kt * 64 + r;
            float4 kv = make_float4(0.f, 0.f, 0.f, 0.f);
            float4 vv = make_float4(0.f, 0.f, 0.f, 0.f);
            if (gr < Sk) {
                kv = *reinterpret_cast<const float4*>(K + koff + (size_t)gr * DIM + c4);
                vv = *reinterpret_cast<const float4*>(V + koff + (size_t)gr * DIM + c4);
            }
            KsT[c4 + 0][r] = kv.x; KsT[c4 + 1][r] = kv.y;
            KsT[c4 + 2][r] = kv.z; KsT[c4 + 3][r] = kv.w;
            *reinterpret_cast<float4*>(&Vs[r][c4]) = vv;
        }
        __syncthreads();

        float s[4][4];
        #pragma unroll
        for (int i = 0; i < 4; i++)
            #pragma unroll
            for (int j = 0; j < 4; j++) s[i][j] = 0.f;
        #pragma unroll 8
        for (int d = 0; d < 64; d++) {
            float qa[4], kb[4];
            *reinterpret_cast<float4*>(qa) = *reinterpret_cast<const float4*>(&QsT[d][tq * 4]);
            *reinterpret_cast<float4*>(kb) = *reinterpret_cast<const float4*>(&KsT[d][tk * 4]);
            #pragma unroll
            for (int i = 0; i < 4; i++)
                #pragma unroll
                for (int j = 0; j < 4; j++)
                    s[i][j] += qa[i] * kb[j];
        }
        #pragma unroll
        for (int qq = 0; qq < 4; qq++)
            #pragma unroll
            for (int kk = 0; kk < 4; kk++) {
                float sv = s[qq][kk] * ATTN_SCALE;
                if (kt * 64 + tk * 4 + kk >= Sk) sv = -1e30f;
                s[qq][kk] = sv;
            }

        float corr[4];
        #pragma unroll
        for (int qq = 0; qq < 4; qq++) {
            float rmax = fmaxf(fmaxf(s[qq][0], s[qq][1]), fmaxf(s[qq][2], s[qq][3]));
            #pragma unroll
            for (int w = 1; w < 16; w <<= 1)
                rmax = fmaxf(rmax, __shfl_xor_sync(0xffffffffu, rmax, w));
            const float mn = fmaxf(m[qq], rmax);
            const float c = __expf(m[qq] - mn);
            float rs = 0.f;
            #pragma unroll
            for (int kk = 0; kk < 4; kk++) {
                const float p = __expf(s[qq][kk] - mn);
                s[qq][kk] = p; rs += p;
            }
            #pragma unroll
            for (int w = 1; w < 16; w <<= 1)
                rs += __shfl_xor_sync(0xffffffffu, rs, w);
            l[qq] = l[qq] * c + rs;
            m[qq] = mn;
            corr[qq] = c;
        }
        #pragma unroll
        for (int kk = 0; kk < 4; kk++)
            #pragma unroll
            for (int qq = 0; qq < 4; qq++)
                PsT[tk * 4 + kk][tq * 4 + qq] = s[qq][kk];
        #pragma unroll
        for (int qq = 0; qq < 4; qq++)
            #pragma unroll
            for (int dd = 0; dd < 4; dd++)
                o[qq][dd] *= corr[qq];
        __syncthreads();

        #pragma unroll 8
        for (int j = 0; j < 64; j++) {
            float pa[4], vb[4];
            *reinterpret_cast<float4*>(pa) = *reinterpret_cast<const float4*>(&PsT[j][tq * 4]);
            *reinterpret_cast<float4*>(vb) = *reinterpret_cast<const float4*>(&Vs[j][tk * 4]);
            #pragma unroll
            for (int qq = 0; qq < 4; qq++)
                #pragma unroll
                for (int dd = 0; dd < 4; dd++)
                    o[qq][dd] += pa[qq] * vb[dd];
        }
    }

    #pragma unroll
    for (int qq = 0; qq < 4; qq++) {
        const float inv = 1.f / l[qq];
        float4 v;
        v.x = o[qq][0] * inv; v.y = o[qq][1] * inv;
        v.z = o[qq][2] * inv; v.w = o[qq][3] * inv;
        *reinterpret_cast<float4*>(
            O + qoff + (size_t)(q0 + tq * 4 + qq) * DIM + tk * 4) = v;
    }
}

// ---------------------------------------------------------------------------
// GEGLU (unchanged)
// ---------------------------------------------------------------------------
__device__ __forceinline__ float gelu_tanh(float x) {
    const float x3 = x * x * x;
    return 0.5f * x * (1.f + tanhf(0.7978845608028654f * (x + 0.044715f * x3)));
}

__global__ __launch_bounds__(256) void geglu_kernel(
    const float* __restrict__ ff, float* __restrict__ out)
{
    const int r = blockIdx.y;
    const int c = (blockIdx.x * 256 + threadIdx.x) << 2;
    const float4 lin = *reinterpret_cast<const float4*>(ff + (size_t)r * (2 * FFI) + c);
    const float4 gt  = *reinterpret_cast<const float4*>(ff + (size_t)r * (2 * FFI) + FFI + c);
    float4 o;
    o.x = lin.x * gelu_tanh(gt.x);
    o.y = lin.y * gelu_tanh(gt.y);
    o.z = lin.z * gelu_tanh(gt.z);
    o.w = lin.w * gelu_tanh(gt.w);
    *reinterpret_cast<float4*>(out + (size_t)r * FFI + c) = o;
}

// ---------------------------------------------------------------------------
// Launch sequence
// ---------------------------------------------------------------------------
extern "C" void kernel_launch(void* const* d_in, const int* in_sizes, int n_in,
                              void* d_out, int out_size)
{
    const float* hs   = (const float*)d_in[0];
    const float* ctx  = (const float*)d_in[1];
    const float* wq1  = (const float*)d_in[2];
    const float* wk1  = (const float*)d_in[3];
    const float* wv1  = (const float*)d_in[4];
    const float* wo1  = (const float*)d_in[5];
    const float* bo1  = (const float*)d_in[6];
    const float* wq2  = (const float*)d_in[7];
    const float* wk2  = (const float*)d_in[8];
    const float* wv2  = (const float*)d_in[9];
    const float* wo2  = (const float*)d_in[10];
    const float* bo2  = (const float*)d_in[11];
    const float* wff1 = (const float*)d_in[12];
    const float* bff1 = (const float*)d_in[13];
    const float* wff2 = (const float*)d_in[14];
    const float* bff2 = (const float*)d_in[15];
    const float* ln1g = (const float*)d_in[16];
    const float* ln1b = (const float*)d_in[17];
    const float* ln2g = (const float*)d_in[18];
    const float* ln2b = (const float*)d_in[19];
    const float* ln3g = (const float*)d_in[20];
    const float* ln3b = (const float*)d_in[21];
    float* out = (float*)d_out;

    float *xn, *q, *k, *v, *attnb, *h, *ff, *gg;
    cudaGetSymbolAddress((void**)&xn,    g_xn);
    cudaGetSymbolAddress((void**)&q,     g_q);
    cudaGetSymbolAddress((void**)&k,     g_k);
    cudaGetSymbolAddress((void**)&v,     g_v);
    cudaGetSymbolAddress((void**)&attnb, g_attn);
    cudaGetSymbolAddress((void**)&h,     g_h);
    cudaGetSymbolAddress((void**)&ff,    g_ff);
    cudaGetSymbolAddress((void**)&gg,    g_gg);

    static bool attr_set = false;
    if (!attr_set) {
        cudaFuncSetAttribute(attn_kernel,
                             cudaFuncAttributeMaxDynamicSharedMemorySize,
                             ATTN_SMEM_BYTES);
        attr_set = true;
    }

    const dim3 blk(256);
    const dim3 g_1024(DIM / 128, BROWS / 128);          // (8, 64)
    const dim3 g_ctx (DIM / 128, (CROWS + 127) / 128);  // (8, 3)
    const dim3 g_ff1 ((2 * FFI) / 128, BROWS / 128);    // (64, 64)
    const dim3 g_attng(SEQ / 64, NHEADS, 4);            // (32, 16, 4)

    // ---- self-attention block ----
    ln_kernel<<<BROWS, blk>>>(hs, xn, ln1g, ln1b);
    gemm_tf32<<<g_1024, blk>>>(xn, wq1, nullptr, nullptr, q, BROWS, DIM, DIM);
    gemm_tf32<<<g_1024, blk>>>(xn, wk1, nullptr, nullptr, k, BROWS, DIM, DIM);
    gemm_tf32<<<g_1024, blk>>>(xn, wv1, nullptr, nullptr, v, BROWS, DIM, DIM);
    attn_kernel<<<g_attng, blk, ATTN_SMEM_BYTES>>>(q, k, v, attnb, SEQ, SEQ);
    gemm_tf32<<<g_1024, blk>>>(attnb, wo1, bo1, hs, h, BROWS, DIM, DIM);

    // ---- cross-attention block ----
    ln_kernel<<<BROWS, blk>>>(h, xn, ln2g, ln2b);
    gemm_tf32<<<g_1024, blk>>>(xn, wq2, nullptr, nullptr, q, BROWS, DIM, DIM);
    gemm_tf32<<<g_ctx,  blk>>>(ctx, wk2, nullptr, nullptr, k, CROWS, DIM, CTXD);
    gemm_tf32<<<g_ctx,  blk>>>(ctx, wv2, nullptr, nullptr, v, CROWS, DIM, CTXD);
    attn_kernel<<<g_attng, blk, ATTN_SMEM_BYTES>>>(q, k, v, attnb, SEQ, TCTX);
    gemm_tf32<<<g_1024, blk>>>(attnb, wo2, bo2, h, h, BROWS, DIM, DIM);

    // ---- GEGLU feed-forward ----
    ln_kernel<<<BROWS, blk>>>(h, xn, ln3g, ln3b);
    gemm_tf32<<<g_ff1, blk>>>(xn, wff1, bff1, nullptr, ff, BROWS, 2 * FFI, DIM);
    geglu_kernel<<<dim3(FFI / 1024, BROWS), blk>>>(ff, gg);
    gemm_tf32<<<g_1024, blk>>>(gg, wff2, bff2, h, out, BROWS, DIM, FFI);
}

// round 3
// speedup vs baseline: 3.7504x; 2.2124x over previous
#include <cuda_runtime.h>
#include <cuda_bf16.h>
#include <cstdint>
#include <cstddef>

// ---------------------------------------------------------------------------
#define BROWS   8192
#define CROWS   308
#define DIM     1024
#define CTXD    768
#define FFI     4096
#define SEQ     2048
#define TCTX    77
#define NHEADS  16
#define DHEAD   64
#define ATTN_SCALE 0.125f

// ---------------------------------------------------------------------------
// Scratch
// ---------------------------------------------------------------------------
__device__ float g_xn  [(size_t)BROWS * DIM];
__device__ float g_q   [(size_t)BROWS * DIM];
__device__ float g_k   [(size_t)BROWS * DIM];
__device__ float g_v   [(size_t)BROWS * DIM];
__device__ float g_attn[(size_t)BROWS * DIM];
__device__ float g_h   [(size_t)BROWS * DIM];
__device__ float g_ff  [(size_t)BROWS * 2 * FFI];
__device__ float g_gg  [(size_t)BROWS * FFI];

// rounded weights + context (tf32-rna in fp32 container)
#define OWQ1 0
#define OWK1 1048576
#define OWV1 2097152
#define OWO1 3145728
#define OWQ2 4194304
#define OWK2 5242880
#define OWV2 6029312
#define OWO2 6815744
#define OWF1 7864320
#define OWF2 16252928
#define OCTX 20447232
#define WRTOT 20683776
__device__ float g_wr[WRTOT];

// ---------------------------------------------------------------------------
// helpers
// ---------------------------------------------------------------------------
__device__ __forceinline__ float tf32r(float f) {
    unsigned u; asm("cvt.rna.tf32.f32 %0, %1;" : "=r"(u) : "f"(f));
    return __uint_as_float(u);
}
__device__ __forceinline__ void mma_f(float c[4], const float a[4], const float b[2]) {
    asm volatile(
        "mma.sync.aligned.m16n8k8.row.col.f32.tf32.tf32.f32 "
        "{%0,%1,%2,%3}, {%4,%5,%6,%7}, {%8,%9}, {%0,%1,%2,%3};\n"
        : "+f"(c[0]), "+f"(c[1]), "+f"(c[2]), "+f"(c[3])
        : "r"(__float_as_uint(a[0])), "r"(__float_as_uint(a[1])),
          "r"(__float_as_uint(a[2])), "r"(__float_as_uint(a[3])),
          "r"(__float_as_uint(b[0])), "r"(__float_as_uint(b[1])));
}
__device__ __forceinline__ void ldsm_x4(unsigned r[4], uint32_t addr) {
    asm volatile("ldmatrix.sync.aligned.m8n8.x4.shared.b16 {%0,%1,%2,%3}, [%4];"
                 : "=r"(r[0]), "=r"(r[1]), "=r"(r[2]), "=r"(r[3]) : "r"(addr));
}
__device__ __forceinline__ void cpa16(uint32_t dst, const void* src, bool pred) {
    int sz = pred ? 16 : 0;
    asm volatile("cp.async.cg.shared.global [%0], [%1], 16, %2;\n"
                 :: "r"(dst), "l"(src), "r"(sz));
}
__device__ __forceinline__ void cpa_commit() { asm volatile("cp.async.commit_group;"); }
template<int N> __device__ __forceinline__ void cpa_wait() {
    asm volatile("cp.async.wait_group %0;" :: "n"(N));
}

// ---------------------------------------------------------------------------
// Weight/context rounding pass (tf32-rna), 11 jobs
// ---------------------------------------------------------------------------
struct RJobs { const float* src[11]; float* dst[11]; int n[11]; };

__global__ __launch_bounds__(256) void round_kernel(RJobs j) {
    const int job = blockIdx.y;
    const float* s = j.src[job];
    float* d = j.dst[job];
    const int n = j.n[job];
    for (int i = (blockIdx.x * 256 + threadIdx.x) * 4; i < n; i += gridDim.x * 1024) {
        float4 v = *reinterpret_cast<const float4*>(s + i);
        v.x = tf32r(v.x); v.y = tf32r(v.y); v.z = tf32r(v.z); v.w = tf32r(v.w);
        *reinterpret_cast<float4*>(d + i) = v;
    }
}

// ---------------------------------------------------------------------------
// LayerNorm (rounds output to tf32 — feeds only GEMM A operands)
// ---------------------------------------------------------------------------
__global__ __launch_bounds__(256) void ln_kernel(
    const float* __restrict__ x, float* __restrict__ y,
    const float* __restrict__ gam, const float* __restrict__ bet)
{
    __shared__ float red[16];
    const int row = blockIdx.x;
    const int t = threadIdx.x;
    const float4 xv = reinterpret_cast<const float4*>(x + (size_t)row * DIM)[t];

    float s  = xv.x + xv.y + xv.z + xv.w;
    float sq = xv.x*xv.x + xv.y*xv.y + xv.z*xv.z + xv.w*xv.w;
    #pragma unroll
    for (int w = 16; w > 0; w >>= 1) {
        s  += __shfl_xor_sync(0xffffffffu, s,  w);
        sq += __shfl_xor_sync(0xffffffffu, sq, w);
    }
    const int wid = t >> 5, lid = t & 31;
    if (lid == 0) { red[wid] = s; red[8 + wid] = sq; }
    __syncthreads();
    if (t < 32) {
        float a  = (lid < 8) ? red[lid]     : 0.f;
        float aq = (lid < 8) ? red[8 + lid] : 0.f;
        #pragma unroll
        for (int w = 4; w > 0; w >>= 1) {
            a  += __shfl_xor_sync(0xffffffffu, a,  w);
            aq += __shfl_xor_sync(0xffffffffu, aq, w);
        }
        if (lid == 0) { red[0] = a; red[8] = aq; }
    }
    __syncthreads();
    const float mean = red[0] * (1.f / DIM);
    const float var  = red[8] * (1.f / DIM) - mean * mean;
    const float inv  = rsqrtf(var + 1e-5f);

    const float4 gv = reinterpret_cast<const float4*>(gam)[t];
    const float4 bv = reinterpret_cast<const float4*>(bet)[t];
    float4 o;
    o.x = tf32r((xv.x - mean) * inv * gv.x + bv.x);
    o.y = tf32r((xv.y - mean) * inv * gv.y + bv.y);
    o.z = tf32r((xv.z - mean) * inv * gv.z + bv.z);
    o.w = tf32r((xv.w - mean) * inv * gv.w + bv.w);
    reinterpret_cast<float4*>(y + (size_t)row * DIM)[t] = o;
}

// ---------------------------------------------------------------------------
// GEMM v3: cp.async 3-stage, ldmatrix A frags, tf32 mma (operands pre-rounded)
// C[M,N] = A[M,K] @ W[K,N] (+bias) (+res) [optionally rounded]
// CTA 128x128x32, 8 warps (2x4). grid.z batches over GemmB slots.
// ---------------------------------------------------------------------------
struct GemmB {
    const float* W[3];
    const float* bias[3];
    const float* res[3];
    float* C[3];
};

#define NSTG 3
#define A_STG 4096                 // floats per A stage (128 rows * 32)
#define B_STG 4352                 // floats per B stage (32 rows * 136)
#define GEMM_SMEM ((NSTG * (A_STG + B_STG)) * 4)   // 101376 B

__global__ __launch_bounds__(256, 2) void gemm_tf32_v3(
    const float* __restrict__ A, GemmB gb, int M, int N, int K, int round_out)
{
    extern __shared__ float smf[];
    const int z = blockIdx.z;
    const float* W    = gb.W[z];
    const float* bias = gb.bias[z];
    const float* res  = gb.res[z];
    float* C          = gb.C[z];

    const int tid = threadIdx.x, warp = tid >> 5, lane = tid & 31;
    const int grp = lane >> 2, tig = lane & 3;
    const int wm = (warp & 1) * 64, wn = (warp >> 1) * 32;
    const int m0 = blockIdx.y << 7, n0 = blockIdx.x << 7;

    const uint32_t smem_u = (uint32_t)__cvta_generic_to_shared(smf);
    const int arow = tid >> 3, ak4 = tid & 7;   // A: 4 chunks, rows arow+32i
    const int brow = tid >> 5, bnc = tid & 31;  // B: 4 chunks, rows brow+8i

    auto issue = [&](int k0, int slot) {
        const uint32_t abase = smem_u + slot * (A_STG * 4);
        #pragma unroll
        for (int i = 0; i < 4; i++) {
            const int row = arow + i * 32;
            const bool ok = (m0 + row) < M;
            const int gr = ok ? (m0 + row) : (M - 1);
            const uint32_t dst = abase + row * 128 + ((ak4 ^ (row & 7)) << 4);
            cpa16(dst, A + (size_t)gr * K + k0 + ak4 * 4, ok);
        }
        const uint32_t bbase = smem_u + NSTG * A_STG * 4 + slot * (B_STG * 4);
        #pragma unroll
        for (int i = 0; i < 4; i++) {
            const int row = brow + i * 8;
            const uint32_t dst = bbase + row * 544 + bnc * 16;
            cpa16(dst, W + (size_t)(k0 + row) * N + n0 + bnc * 4, true);
        }
        cpa_commit();
    };

    float acc[4][4][4];
    #pragma unroll
    for (int i = 0; i < 4; i++)
        #pragma unroll
        for (int j = 0; j < 4; j++)
            #pragma unroll
            for (int r = 0; r < 4; r++) acc[i][j][r] = 0.f;

    issue(0, 0);
    issue(32, 1);

    const int niter = K >> 5;
    for (int it = 0; it < niter; it++) {
        if (it + 1 < niter) cpa_wait<1>(); else cpa_wait<0>();
        __syncthreads();
        if (it + 2 < niter) issue((it + 2) * 32, (it + 2) % 3);

        const int slot = it % 3;
        const uint32_t ab = smem_u + slot * (A_STG * 4);
        const float* bsl = smf + NSTG * A_STG + slot * B_STG;

        #pragma unroll
        for (int ks8 = 0; ks8 < 4; ks8++) {
            const int kk = ks8 * 8;
            float a[4][4];
            #pragma unroll
            for (int mi = 0; mi < 4; mi++) {
                const int row = wm + mi * 16 + (lane & 7) + ((lane >> 3) & 1) * 8;
                const int k4 = (kk >> 2) + (lane >> 4);
                ldsm_x4(reinterpret_cast<unsigned*>(a[mi]),
                        ab + row * 128 + ((k4 ^ (row & 7)) << 4));
            }
            #pragma unroll
            for (int nj = 0; nj < 4; nj++) {
                float b[2];
                const float* bp = bsl + (kk + tig) * 136 + wn + nj * 8 + grp;
                b[0] = bp[0];
                b[1] = bp[4 * 136];
                #pragma unroll
                for (int mi = 0; mi < 4; mi++)
                    mma_f(acc[mi][nj], a[mi], b);
            }
        }
        __syncthreads();
    }

    #pragma unroll
    for (int mi = 0; mi < 4; mi++) {
        #pragma unroll
        for (int half = 0; half < 2; half++) {
            const int r = m0 + wm + mi * 16 + grp + half * 8;
            if (r >= M) continue;
            #pragma unroll
            for (int nj = 0; nj < 4; nj++) {
                const int c = n0 + wn + nj * 8 + tig * 2;
                float2 v;
                v.x = acc[mi][nj][half * 2 + 0];
                v.y = acc[mi][nj][half * 2 + 1];
                if (bias) { v.x += bias[c]; v.y += bias[c + 1]; }
                if (res) {
                    const float2 rv = *reinterpret_cast<const float2*>(res + (size_t)r * N + c);
                    v.x += rv.x; v.y += rv.y;
                }
                if (round_out) { v.x = tf32r(v.x); v.y = tf32r(v.y); }
                *reinterpret_cast<float2*>(C + (size_t)r * N + c) = v;
            }
        }
    }
}

// ---------------------------------------------------------------------------
// tf32 flash attention. Q/K/V/O: [B*S, 16*64] row-major, pre-rounded tf32.
// Block = 128 q rows, 8 warps x 16 q. K/V 64-row tiles, cp.async double buffer.
// smem floats: Qs/Ps [128][68] @0 ; Ks [2][64][68] @8704 ; Vs [2][64][72] @17408
// ---------------------------------------------------------------------------
#define ATTN_SMEM (26624 * 4)

__global__ __launch_bounds__(256, 2) void attn_tf32(
    const float* __restrict__ Q, const float* __restrict__ K,
    const float* __restrict__ V, float* __restrict__ O, int Sq, int Sk)
{
    extern __shared__ float sm[];
    float* Qs = sm;                      // aliased as Ps after Q consumed
    const int tid = threadIdx.x, warp = tid >> 5, lane = tid & 31;
    const int grp = lane >> 2, tig = lane & 3;
    const int h = blockIdx.y, b = blockIdx.z;
    const int q0 = blockIdx.x * 128;
    const size_t qoff = (size_t)b * Sq * DIM + (size_t)h * DHEAD;
    const size_t koff = (size_t)b * Sk * DIM + (size_t)h * DHEAD;
    const int rbase = warp * 16;

    const uint32_t smem_u = (uint32_t)__cvta_generic_to_shared(sm);
    const uint32_t ks_u = smem_u + 8704 * 4;
    const uint32_t vs_u = smem_u + 17408 * 4;

    auto issue_kv = [&](int kt, int slot) {
        #pragma unroll
        for (int i = 0; i < 4; i++) {
            const int c = tid + i * 256;
            const int row = c >> 4, nc = c & 15;
            const int gr = kt * 64 + row;
            const bool ok = gr < Sk;
            const int grc = ok ? gr : 0;
            cpa16(ks_u + slot * (4352 * 4) + row * 272 + nc * 16,
                  K + koff + (size_t)grc * DIM + nc * 4, ok);
        }
        #pragma unroll
        for (int i = 0; i < 4; i++) {
            const int c = tid + i * 256;
            const int row = c >> 4, nc = c & 15;
            const int gr = kt * 64 + row;
            const bool ok = gr < Sk;
            const int grc = ok ? gr : 0;
            cpa16(vs_u + slot * (4608 * 4) + row * 288 + nc * 16,
                  V + koff + (size_t)grc * DIM + nc * 4, ok);
        }
        cpa_commit();
    };

    // Q tile load (group 0)
    #pragma unroll
    for (int i = 0; i < 8; i++) {
        const int c = tid + i * 256;
        const int row = c >> 4, nc = c & 15;
        cpa16(smem_u + row * 272 + nc * 16,
              Q + qoff + (size_t)(q0 + row) * DIM + nc * 4, true);
    }
    cpa_commit();
    issue_kv(0, 0);

    float qa[8][4];
    float o[8][4];
    #pragma unroll
    for (int d = 0; d < 8; d++)
        #pragma unroll
        for (int r = 0; r < 4; r++) o[d][r] = 0.f;
    float mx0 = -1e30f, mx1 = -1e30f, l0 = 0.f, l1 = 0.f;

    const int nkt = (Sk + 63) >> 6;
    for (int kt = 0; kt < nkt; kt++) {
        if (kt + 1 < nkt) { issue_kv(kt + 1, (kt + 1) & 1); cpa_wait<1>(); }
        else cpa_wait<0>();
        __syncthreads();

        if (kt == 0) {   // pull Q into registers (scale folded; exact pow2)
            #pragma unroll
            for (int ks = 0; ks < 8; ks++) {
                const float* qp = Qs + (rbase + grp) * 68 + ks * 8 + tig;
                qa[ks][0] = qp[0]        * ATTN_SCALE;
                qa[ks][1] = qp[8 * 68]   * ATTN_SCALE;
                qa[ks][2] = qp[4]        * ATTN_SCALE;
                qa[ks][3] = qp[8 * 68 + 4] * ATTN_SCALE;
            }
            __syncthreads();   // Qs free for reuse as Ps
        }

        const float* ksl = sm + 8704 + (kt & 1) * 4352;
        const float* vsl = sm + 17408 + (kt & 1) * 4608;

        // ---- scores S = Q K^T ----
        float sc[8][4];
        #pragma unroll
        for (int nj = 0; nj < 8; nj++)
            #pragma unroll
            for (int r = 0; r < 4; r++) sc[nj][r] = 0.f;

        #pragma unroll
        for (int ks = 0; ks < 8; ks++) {
            #pragma unroll
            for (int nj = 0; nj < 8; nj++) {
                float kb[2];
                const float* kp = ksl + (nj * 8 + grp) * 68 + ks * 8 + tig;
                kb[0] = kp[0];
                kb[1] = kp[4];
                mma_f(sc[nj], qa[ks], kb);
            }
        }

        // mask padded keys (cross-attn tail tile)
        if (kt * 64 + 64 > Sk) {
            #pragma unroll
            for (int nj = 0; nj < 8; nj++) {
                const int j = kt * 64 + nj * 8 + tig * 2;
                if (j     >= Sk) { sc[nj][0] = -1e30f; sc[nj][2] = -1e30f; }
                if (j + 1 >= Sk) { sc[nj][1] = -1e30f; sc[nj][3] = -1e30f; }
            }
        }

        // ---- online softmax: rows grp (regs 0,1) and grp+8 (regs 2,3) ----
        float tm0 = -1e30f, tm1 = -1e30f;
        #pragma unroll
        for (int nj = 0; nj < 8; nj++) {
            tm0 = fmaxf(tm0, fmaxf(sc[nj][0], sc[nj][1]));
            tm1 = fmaxf(tm1, fmaxf(sc[nj][2], sc[nj][3]));
        }
        tm0 = fmaxf(tm0, __shfl_xor_sync(0xffffffffu, tm0, 1));
        tm0 = fmaxf(tm0, __shfl_xor_sync(0xffffffffu, tm0, 2));
        tm1 = fmaxf(tm1, __shfl_xor_sync(0xffffffffu, tm1, 1));
        tm1 = fmaxf(tm1, __shfl_xor_sync(0xffffffffu, tm1, 2));
        const float mn0 = fmaxf(mx0, tm0), mn1 = fmaxf(mx1, tm1);
        const float c0 = __expf(mx0 - mn0), c1 = __expf(mx1 - mn1);
        mx0 = mn0; mx1 = mn1;
        float s0 = 0.f, s1 = 0.f;
        #pragma unroll
        for (int nj = 0; nj < 8; nj++) {
            sc[nj][0] = __expf(sc[nj][0] - mn0);
            sc[nj][1] = __expf(sc[nj][1] - mn0);
            sc[nj][2] = __expf(sc[nj][2] - mn1);
            sc[nj][3] = __expf(sc[nj][3] - mn1);
            s0 += sc[nj][0] + sc[nj][1];
            s1 += sc[nj][2] + sc[nj][3];
        }
        s0 += __shfl_xor_sync(0xffffffffu, s0, 1);
        s0 += __shfl_xor_sync(0xffffffffu, s0, 2);
        s1 += __shfl_xor_sync(0xffffffffu, s1, 1);
        s1 += __shfl_xor_sync(0xffffffffu, s1, 2);
        l0 = l0 * c0 + s0;
        l1 = l1 * c1 + s1;
        #pragma unroll
        for (int d = 0; d < 8; d++) {
            o[d][0] *= c0; o[d][1] *= c0;
            o[d][2] *= c1; o[d][3] *= c1;
        }

        // ---- publish P (tf32-rounded) to smem, per-warp region ----
        float* Ps = Qs;
        #pragma unroll
        for (int nj = 0; nj < 8; nj++) {
            float2 p01; p01.x = tf32r(sc[nj][0]); p01.y = tf32r(sc[nj][1]);
            *reinterpret_cast<float2*>(Ps + (rbase + grp) * 68 + nj * 8 + tig * 2) = p01;
            float2 p23; p23.x = tf32r(sc[nj][2]); p23.y = tf32r(sc[nj][3]);
            *reinterpret_cast<float2*>(Ps + (rbase + grp + 8) * 68 + nj * 8 + tig * 2) = p23;
        }
        __syncwarp();

        // ---- O += P V ----
        #pragma unroll
        for (int kj = 0; kj < 8; kj++) {
            float pa[4];
            const float* pp = Ps + (rbase + grp) * 68 + kj * 8 + tig;
            pa[0] = pp[0];
            pa[1] = pp[8 * 68];
            pa[2] = pp[4];
            pa[3] = pp[8 * 68 + 4];
            #pragma unroll
            for (int d = 0; d < 8; d++) {
                float vb[2];
                const float* vp = vsl + (kj * 8 + tig) * 72 + d * 8 + grp;
                vb[0] = vp[0];
                vb[1] = vp[4 * 72];
                mma_f(o[d], pa, vb);
            }
        }
        __syncthreads();
    }

    const float i0 = 1.f / l0, i1 = 1.f / l1;
    #pragma unroll
    for (int d = 0; d < 8; d++) {
        float2 v0; v0.x = tf32r(o[d][0] * i0); v0.y = tf32r(o[d][1] * i0);
        *reinterpret_cast<float2*>(
            O + qoff + (size_t)(q0 + rbase + grp) * DIM + d * 8 + tig * 2) = v0;
        float2 v1; v1.x = tf32r(o[d][2] * i1); v1.y = tf32r(o[d][3] * i1);
        *reinterpret_cast<float2*>(
            O + qoff + (size_t)(q0 + rbase + grp + 8) * DIM + d * 8 + tig * 2) = v1;
    }
}

// ---------------------------------------------------------------------------
// GEGLU (rounds output — feeds FF2 A operand)
// ---------------------------------------------------------------------------
__device__ __forceinline__ float gelu_tanh(float x) {
    const float x3 = x * x * x;
    return 0.5f * x * (1.f + tanhf(0.7978845608028654f * (x + 0.044715f * x3)));
}

__global__ __launch_bounds__(256) void geglu_kernel(
    const float* __restrict__ ff, float* __restrict__ out)
{
    const int r = blockIdx.y;
    const int c = (blockIdx.x * 256 + threadIdx.x) << 2;
    const float4 lin = *reinterpret_cast<const float4*>(ff + (size_t)r * (2 * FFI) + c);
    const float4 gt  = *reinterpret_cast<const float4*>(ff + (size_t)r * (2 * FFI) + FFI + c);
    float4 o;
    o.x = tf32r(lin.x * gelu_tanh(gt.x));
    o.y = tf32r(lin.y * gelu_tanh(gt.y));
    o.z = tf32r(lin.z * gelu_tanh(gt.z));
    o.w = tf32r(lin.w * gelu_tanh(gt.w));
    *reinterpret_cast<float4*>(out + (size_t)r * FFI + c) = o;
}

// ---------------------------------------------------------------------------
extern "C" void kernel_launch(void* const* d_in, const int* in_sizes, int n_in,
                              void* d_out, int out_size)
{
    const float* hs   = (const float*)d_in[0];
    const float* ctx  = (const float*)d_in[1];
    const float* wq1  = (const float*)d_in[2];
    const float* wk1  = (const float*)d_in[3];
    const float* wv1  = (const float*)d_in[4];
    const float* wo1  = (const float*)d_in[5];
    const float* bo1  = (const float*)d_in[6];
    const float* wq2  = (const float*)d_in[7];
    const float* wk2  = (const float*)d_in[8];
    const float* wv2  = (const float*)d_in[9];
    const float* wo2  = (const float*)d_in[10];
    const float* bo2  = (const float*)d_in[11];
    const float* wff1 = (const float*)d_in[12];
    const float* bff1 = (const float*)d_in[13];
    const float* wff2 = (const float*)d_in[14];
    const float* bff2 = (const float*)d_in[15];
    const float* ln1g = (const float*)d_in[16];
    const float* ln1b = (const float*)d_in[17];
    const float* ln2g = (const float*)d_in[18];
    const float* ln2b = (const float*)d_in[19];
    const float* ln3g = (const float*)d_in[20];
    const float* ln3b = (const float*)d_in[21];
    float* out = (float*)d_out;

    float *xn, *q, *k, *v, *attnb, *h, *ff, *gg, *wr;
    cudaGetSymbolAddress((void**)&xn,    g_xn);
    cudaGetSymbolAddress((void**)&q,     g_q);
    cudaGetSymbolAddress((void**)&k,     g_k);
    cudaGetSymbolAddress((void**)&v,     g_v);
    cudaGetSymbolAddress((void**)&attnb, g_attn);
    cudaGetSymbolAddress((void**)&h,     g_h);
    cudaGetSymbolAddress((void**)&ff,    g_ff);
    cudaGetSymbolAddress((void**)&gg,    g_gg);
    cudaGetSymbolAddress((void**)&wr,    g_wr);

    cudaFuncSetAttribute(gemm_tf32_v3, cudaFuncAttributeMaxDynamicSharedMemorySize, GEMM_SMEM);
    cudaFuncSetAttribute(attn_tf32,    cudaFuncAttributeMaxDynamicSharedMemorySize, ATTN_SMEM);

    // ---- round weights + context to tf32 ----
    RJobs rj;
    const float* srcs[11] = {wq1, wk1, wv1, wo1, wq2, wk2, wv2, wo2, wff1, wff2, ctx};
    const int    offs[11] = {OWQ1, OWK1, OWV1, OWO1, OWQ2, OWK2, OWV2, OWO2, OWF1, OWF2, OCTX};
    const int    lens[11] = {1048576, 1048576, 1048576, 1048576, 1048576, 786432, 786432,
                             1048576, 8388608, 4194304, 236544};
    for (int i = 0; i < 11; i++) { rj.src[i] = srcs[i]; rj.dst[i] = wr + offs[i]; rj.n[i] = lens[i]; }
    round_kernel<<<dim3(512, 11), 256>>>(rj);

    const dim3 blk(256);
    const dim3 g_attng(SEQ / 128, NHEADS, 4);

    GemmB gqkv; GemmB gwo1; GemmB gq2; GemmB gkv2; GemmB gwo2; GemmB gff1; GemmB gff2;
    for (int i = 0; i < 3; i++) {
        gqkv.bias[i] = nullptr; gqkv.res[i] = nullptr;
        gkv2.bias[i] = nullptr; gkv2.res[i] = nullptr;
        gq2.bias[i] = nullptr;  gq2.res[i] = nullptr;
        gff1.bias[i] = nullptr; gff1.res[i] = nullptr;
        gwo1.bias[i] = nullptr; gwo1.res[i] = nullptr;
        gwo2.bias[i] = nullptr; gwo2.res[i] = nullptr;
        gff2.bias[i] = nullptr; gff2.res[i] = nullptr;
        gqkv.W[i] = gwo1.W[i] = gq2.W[i] = gkv2.W[i] = gwo2.W[i] = gff1.W[i] = gff2.W[i] = nullptr;
        gqkv.C[i] = gwo1.C[i] = gq2.C[i] = gkv2.C[i] = gwo2.C[i] = gff1.C[i] = gff2.C[i] = nullptr;
    }
    gqkv.W[0] = wr + OWQ1; gqkv.C[0] = q;
    gqkv.W[1] = wr + OWK1; gqkv.C[1] = k;
    gqkv.W[2] = wr + OWV1; gqkv.C[2] = v;
    gwo1.W[0] = wr + OWO1; gwo1.bias[0] = bo1; gwo1.res[0] = hs; gwo1.C[0] = h;
    gq2.W[0]  = wr + OWQ2; gq2.C[0]  = q;
    gkv2.W[0] = wr + OWK2; gkv2.C[0] = k;
    gkv2.W[1] = wr + OWV2; gkv2.C[1] = v;
    gwo2.W[0] = wr + OWO2; gwo2.bias[0] = bo2; gwo2.res[0] = h; gwo2.C[0] = h;
    gff1.W[0] = wr + OWF1; gff1.bias[0] = bff1; gff1.C[0] = ff;
    gff2.W[0] = wr + OWF2; gff2.bias[0] = bff2; gff2.res[0] = h; gff2.C[0] = out;

    // ---- self-attention ----
    ln_kernel<<<BROWS, blk>>>(hs, xn, ln1g, ln1b);
    gemm_tf32_v3<<<dim3(8, 64, 3), blk, GEMM_SMEM>>>(xn, gqkv, BROWS, DIM, DIM, 1);
    attn_tf32<<<g_attng, blk, ATTN_SMEM>>>(q, k, v, attnb, SEQ, SEQ);
    gemm_tf32_v3<<<dim3(8, 64, 1), blk, GEMM_SMEM>>>(attnb, gwo1, BROWS, DIM, DIM, 0);

    // ---- cross-attention ----
    ln_kernel<<<BROWS, blk>>>(h, xn, ln2g, ln2b);
    gemm_tf32_v3<<<dim3(8, 64, 1), blk, GEMM_SMEM>>>(xn, gq2, BROWS, DIM, DIM, 1);
    gemm_tf32_v3<<<dim3(8, 3, 2), blk, GEMM_SMEM>>>(wr + OCTX, gkv2, CROWS, DIM, CTXD, 1);
    attn_tf32<<<g_attng, blk, ATTN_SMEM>>>(q, k, v, attnb, SEQ, TCTX);
    gemm_tf32_v3<<<dim3(8, 64, 1), blk, GEMM_SMEM>>>(attnb, gwo2, BROWS, DIM, DIM, 0);

    // ---- GEGLU feed-forward ----
    ln_kernel<<<BROWS, blk>>>(h, xn, ln3g, ln3b);
    gemm_tf32_v3<<<dim3(64, 64, 1), blk, GEMM_SMEM>>>(xn, gff1, BROWS, 2 * FFI, DIM, 0);
    geglu_kernel<<<dim3(FFI / 1024, BROWS), blk>>>(ff, gg);
    gemm_tf32_v3<<<dim3(8, 64, 1), blk, GEMM_SMEM>>>(gg, gff2, BROWS, DIM, FFI, 0);
}